// round 2
// baseline (speedup 1.0000x reference)
#include <cuda_runtime.h>

// AlphaGridMask: stable counting-sort by block id + trilinear grid_sample.
// N = 4,194,304 points, 64 blocks, volume 256^3 f32 viewed as [64][64][64][64].
//
// 3-level stable rank:  dest = binbase[b] + ctabase[b][cta] + intra-CTA thread
// prefix + within-thread running count.  Threads own contiguous 16-point
// segments in original order, so sequential processing preserves stability.

#define SPT    16                // points per thread (contiguous)
#define NBIN   64
#define CTA    128
#define PPC    (SPT * CTA)       // 2048 points per CTA
#define MAXCTA 4096

__device__ unsigned char g_bids[8388608];            // bid per point (orig order)
__device__ unsigned int  g_ctacnt[NBIN * MAXCTA];    // [b][cta] counts -> excl prefix
__device__ unsigned int  g_bintot[NBIN];
__device__ unsigned int  g_binbase[NBIN];

// Bit-exact block id vs reference: IEEE sub, IEEE div, floor, clip to [0,3].
__device__ __forceinline__ int bid_of(float x, float y, float z,
                                      float a0x, float a0y, float a0z,
                                      float vx, float vy, float vz) {
    float qx = __fdiv_rn(x - a0x, vx);
    float qy = __fdiv_rn(y - a0y, vy);
    float qz = __fdiv_rn(z - a0z, vz);
    int ix = (int)floorf(qx);
    int iy = (int)floorf(qy);
    int iz = (int)floorf(qz);
    ix = min(max(ix, 0), 3);
    iy = min(max(iy, 0), 3);
    iz = min(max(iz, 0), 3);
    return (ix << 4) + (iy << 2) + iz;   // strides [16,4,1]
}

// ---------------- Pass 1: bids + per-CTA bin totals ----------------
__global__ void __launch_bounds__(CTA) k_count(const float4* __restrict__ xyz4,
                                               const float* __restrict__ aabb,
                                               int ncta) {
    __shared__ unsigned int hist[NBIN * CTA];   // [b*128+t] -> bank t%32, no conflicts
    __shared__ float s_bb[6];
    int tid = threadIdx.x, cta = blockIdx.x;
    #pragma unroll
    for (int b = 0; b < NBIN; b++) hist[b * CTA + tid] = 0;
    if (tid < 6) s_bb[tid] = aabb[tid];
    __syncthreads();
    float a0x = s_bb[0], a0y = s_bb[1], a0z = s_bb[2];
    float vx = (s_bb[3] - a0x) * 0.25f;   // /4 exact
    float vy = (s_bb[4] - a0y) * 0.25f;
    float vz = (s_bb[5] - a0z) * 0.25f;

    int gthread = cta * CTA + tid;
    const float4* p4 = xyz4 + (size_t)gthread * 12;   // 12 float4 = 16 points
    unsigned int pk[4] = {0, 0, 0, 0};
    #pragma unroll
    for (int g = 0; g < 4; g++) {                     // 4 points per 3 float4
        float4 A = __ldg(p4 + g * 3 + 0);
        float4 B = __ldg(p4 + g * 3 + 1);
        float4 C = __ldg(p4 + g * 3 + 2);
        float xs[4] = {A.x, A.w, B.z, C.y};
        float ys[4] = {A.y, B.x, B.w, C.z};
        float zs[4] = {A.z, B.y, C.x, C.w};
        #pragma unroll
        for (int j = 0; j < 4; j++) {
            int bid = bid_of(xs[j], ys[j], zs[j], a0x, a0y, a0z, vx, vy, vz);
            pk[g] |= (unsigned int)bid << (j * 8);
            hist[bid * CTA + tid]++;
        }
    }
    ((uint4*)g_bids)[gthread] = make_uint4(pk[0], pk[1], pk[2], pk[3]);
    __syncthreads();

    // per-CTA totals: warp w reduces bins [w*16, w*16+16)
    int lane = tid & 31, w = tid >> 5;
    #pragma unroll
    for (int i = 0; i < 16; i++) {
        int b = w * 16 + i;
        const unsigned int* r = hist + b * CTA;
        unsigned int s = r[lane] + r[32 + lane] + r[64 + lane] + r[96 + lane];
        #pragma unroll
        for (int off = 16; off; off >>= 1) s += __shfl_down_sync(0xffffffffu, s, off);
        if (lane == 0) g_ctacnt[(size_t)b * ncta + cta] = s;
    }
}

// ---------------- Pass 2a: per-bin exclusive scan across CTAs ----------------
__global__ void __launch_bounds__(256) k_scan_cta(int ncta) {
    int b = blockIdx.x, tid = threadIdx.x;
    unsigned int* row = g_ctacnt + (size_t)b * ncta;
    int per = (ncta + 255) >> 8;
    int base = tid * per;
    unsigned int s = 0;
    for (int k = 0; k < per; k++) { int i = base + k; if (i < ncta) s += row[i]; }
    __shared__ unsigned int sh[256];
    sh[tid] = s;
    __syncthreads();
    #pragma unroll
    for (int off = 1; off < 256; off <<= 1) {
        unsigned int v = (tid >= off) ? sh[tid - off] : 0;
        __syncthreads();
        if (tid >= off) sh[tid] += v;
        __syncthreads();
    }
    unsigned int incl = sh[tid];
    if (tid == 255) g_bintot[b] = incl;
    unsigned int run = incl - s;
    for (int k = 0; k < per; k++) {
        int i = base + k;
        if (i < ncta) { unsigned int v = row[i]; row[i] = run; run += v; }
    }
}

// ---------------- Pass 2b: scan 64 bin totals ----------------
__global__ void k_scan_bins() {
    int tid = threadIdx.x;
    unsigned int v = g_bintot[tid];
    __shared__ unsigned int sh[64];
    sh[tid] = v;
    __syncthreads();
    for (int off = 1; off < 64; off <<= 1) {
        unsigned int u = (tid >= off) ? sh[tid - off] : 0;
        __syncthreads();
        if (tid >= off) sh[tid] += u;
        __syncthreads();
    }
    g_binbase[tid] = sh[tid] - v;
}

// ---------------- Pass 3: sample + stable scatter ----------------
__global__ void __launch_bounds__(CTA) k_sample(const float4* __restrict__ xyz4,
                                                const float* __restrict__ vol,
                                                const float* __restrict__ dmin,
                                                const float* __restrict__ dmax,
                                                float* __restrict__ out,
                                                int ncta) {
    __shared__ unsigned int offs[NBIN * CTA];   // 32KB, [b*128+t]
    __shared__ float s_org[NBIN * 3];
    __shared__ float s_scl[NBIN * 3];
    __shared__ unsigned int s_cb[NBIN];
    int tid = threadIdx.x, cta = blockIdx.x;

    for (int i = tid; i < NBIN * 3; i += CTA) {
        float dn = dmin[i];
        s_org[i] = dn;
        s_scl[i] = 63.0f / (dmax[i] - dn);      // f = (p-dmin)*63/(dmax-dmin)
    }
    if (tid < NBIN) s_cb[tid] = g_binbase[tid] + g_ctacnt[(size_t)tid * ncta + cta];
    #pragma unroll
    for (int b = 0; b < NBIN; b++) offs[b * CTA + tid] = 0;
    __syncthreads();

    int gthread = cta * CTA + tid;
    uint4 pk = ((const uint4*)g_bids)[gthread];
    unsigned int bw[4] = {pk.x, pk.y, pk.z, pk.w};
    #pragma unroll
    for (int k = 0; k < SPT; k++) {
        int bid = (bw[k >> 2] >> ((k & 3) * 8)) & 0x3f;
        offs[bid * CTA + tid]++;
    }
    __syncthreads();

    // per-bin exclusive scan across threads; warp w handles bins [w*16, w*16+16)
    int lane = tid & 31, w = tid >> 5;
    #pragma unroll
    for (int i = 0; i < 16; i++) {
        int b = w * 16 + i;
        unsigned int* r = offs + b * CTA;
        uint4 v = ((uint4*)r)[lane];            // lane covers threads [4l, 4l+4)
        unsigned int tot = v.x + v.y + v.z + v.w;
        unsigned int inc = tot;
        #pragma unroll
        for (int off = 1; off < 32; off <<= 1) {
            unsigned int u = __shfl_up_sync(0xffffffffu, inc, off);
            if (lane >= off) inc += u;
        }
        unsigned int e = s_cb[b] + inc - tot;   // global base for thread 4l
        uint4 o;
        o.x = e;
        o.y = e + v.x;
        o.z = o.y + v.y;
        o.w = o.z + v.z;
        ((uint4*)r)[lane] = o;
    }
    __syncthreads();

    const float4* p4 = xyz4 + (size_t)gthread * 12;
    #pragma unroll
    for (int g = 0; g < 4; g++) {
        float4 A = __ldg(p4 + g * 3 + 0);
        float4 B = __ldg(p4 + g * 3 + 1);
        float4 C = __ldg(p4 + g * 3 + 2);
        float xs[4] = {A.x, A.w, B.z, C.y};
        float ys[4] = {A.y, B.x, B.w, C.z};
        float zs[4] = {A.z, B.y, C.x, C.w};
        #pragma unroll
        for (int j = 0; j < 4; j++) {
            int bid = (bw[g] >> (j * 8)) & 0x3f;
            int b3 = bid * 3;
            float fx = (xs[j] - s_org[b3 + 0]) * s_scl[b3 + 0];
            float fy = (ys[j] - s_org[b3 + 1]) * s_scl[b3 + 1];
            float fz = (zs[j] - s_org[b3 + 2]) * s_scl[b3 + 2];
            float x0f = floorf(fx), y0f = floorf(fy), z0f = floorf(fz);
            float wx = fx - x0f, wy = fy - y0f, wz = fz - z0f;
            int x0 = (int)x0f, y0 = (int)y0f, z0 = (int)z0f;
            int x0c = min(max(x0, 0), 63), x1c = min(max(x0 + 1, 0), 63);
            int y0c = min(max(y0, 0), 63), y1c = min(max(y0 + 1, 0), 63);
            int z0c = min(max(z0, 0), 63), z1c = min(max(z0 + 1, 0), 63);
            const float* vb = vol + ((size_t)bid << 18);
            int zy00 = ((z0c << 6) + y0c) << 6;
            int zy01 = ((z0c << 6) + y1c) << 6;
            int zy10 = ((z1c << 6) + y0c) << 6;
            int zy11 = ((z1c << 6) + y1c) << 6;
            float v000 = __ldg(vb + zy00 + x0c), v001 = __ldg(vb + zy00 + x1c);
            float v010 = __ldg(vb + zy01 + x0c), v011 = __ldg(vb + zy01 + x1c);
            float v100 = __ldg(vb + zy10 + x0c), v101 = __ldg(vb + zy10 + x1c);
            float v110 = __ldg(vb + zy11 + x0c), v111 = __ldg(vb + zy11 + x1c);
            float omx = 1.0f - wx, omy = 1.0f - wy, omz = 1.0f - wz;
            float res = omz * (omy * (omx * v000 + wx * v001) + wy * (omx * v010 + wx * v011))
                      + wz  * (omy * (omx * v100 + wx * v101) + wy * (omx * v110 + wx * v111));
            unsigned int d = offs[bid * CTA + tid]++;
            out[d] = res;
        }
    }
}

extern "C" void kernel_launch(void* const* d_in, const int* in_sizes, int n_in,
                              void* d_out, int out_size) {
    const float4* xyz4 = (const float4*)d_in[0];
    const float*  aabb = (const float*)d_in[1];
    const float*  vol  = (const float*)d_in[2];
    const float*  dmin = (const float*)d_in[3];
    const float*  dmax = (const float*)d_in[4];
    float* out = (float*)d_out;

    int n = in_sizes[0] / 3;          // 4,194,304
    int ncta = n / PPC;               // 2048

    k_count<<<ncta, CTA>>>(xyz4, aabb, ncta);
    k_scan_cta<<<NBIN, 256>>>(ncta);
    k_scan_bins<<<1, NBIN>>>();
    k_sample<<<ncta, CTA>>>(xyz4, vol, dmin, dmax, out, ncta);
}

// round 3
// speedup vs baseline: 3.1379x; 3.1379x over previous
#include <cuda_runtime.h>

// AlphaGridMask: stable counting-sort by block id + trilinear grid_sample.
// N = 4,194,304 pts, 64 blocks, volume 256^3 f32 viewed as [64][64][64][64].
//
// dest(point) = binbase[bid] + warpbase[bid][gw] + intra-warp stable rank.
// A pass-1 warp owns contiguous 512 points in (round, lane) order, which is
// original order, so ranks computed sequentially per round are exactly stable.

#define NBIN  64
#define CTA1  256
#define NW    8            // warps per CTA
#define RND   16           // rounds per warp -> 512 points per warp
#define SEG   512
#define NGWMAX 8192

__device__ unsigned short g_rank[4194304];          // (bid<<10)|rank per point, 8MB
__device__ unsigned int   g_warpcnt[NBIN * NGWMAX]; // [b][gw] counts -> excl prefix
__device__ unsigned int   g_bintot[NBIN];
__device__ unsigned int   g_binbase[NBIN];

// Bit-exact block id vs reference: IEEE sub, IEEE div, floor, clip to [0,3].
__device__ __forceinline__ int bid_of(float x, float y, float z,
                                      float a0x, float a0y, float a0z,
                                      float vx, float vy, float vz) {
    float qx = __fdiv_rn(x - a0x, vx);
    float qy = __fdiv_rn(y - a0y, vy);
    float qz = __fdiv_rn(z - a0z, vz);
    int ix = (int)floorf(qx);
    int iy = (int)floorf(qy);
    int iz = (int)floorf(qz);
    ix = min(max(ix, 0), 3);
    iy = min(max(iy, 0), 3);
    iz = min(max(iz, 0), 3);
    return (ix << 4) + (iy << 2) + iz;   // strides [16,4,1]
}

// ---------------- Pass 1: bids + stable intra-warp ranks ----------------
__global__ void __launch_bounds__(CTA1) k_bin(const float* __restrict__ xyz,
                                              const float* __restrict__ aabb,
                                              int ngw) {
    __shared__ unsigned int cnt[NW * NBIN];
    __shared__ float s_bb[6];
    int tid = threadIdx.x, w = tid >> 5, lane = tid & 31;
    cnt[tid] = 0;
    cnt[tid + 256] = 0;
    if (tid < 6) s_bb[tid] = aabb[tid];
    __syncthreads();

    float a0x = s_bb[0], a0y = s_bb[1], a0z = s_bb[2];
    float vx = (s_bb[3] - a0x) * 0.25f;   // /4 exact
    float vy = (s_bb[4] - a0y) * 0.25f;
    float vz = (s_bb[5] - a0z) * 0.25f;

    int gw = blockIdx.x * NW + w;
    size_t segbase = (size_t)gw * SEG;
    unsigned int lmlt = (1u << lane) - 1u;
    unsigned int* mycnt = cnt + w * NBIN;

    for (int r = 0; r < RND; r++) {
        size_t p = segbase + (size_t)r * 32 + lane;
        const float* q = xyz + p * 3;
        float x = __ldg(q + 0), y = __ldg(q + 1), z = __ldg(q + 2);
        int bid = bid_of(x, y, z, a0x, a0y, a0z, vx, vy, vz);

        unsigned int mask = __match_any_sync(0xffffffffu, bid);
        int leader = __ffs(mask) - 1;
        unsigned int base = 0;
        if (lane == leader) base = mycnt[bid];
        base = __shfl_sync(0xffffffffu, base, leader);
        unsigned int rank = base + __popc(mask & lmlt);
        if (lane == leader) mycnt[bid] = base + __popc(mask);
        g_rank[p] = (unsigned short)(((unsigned)bid << 10) | rank);
        __syncwarp();
    }

    // per-warp bin totals -> [b][gw]
    g_warpcnt[(size_t)lane * ngw + gw]        = mycnt[lane];
    g_warpcnt[(size_t)(lane + 32) * ngw + gw] = mycnt[lane + 32];
}

// ---------------- Pass 2a: per-bin exclusive scan across warps ----------------
__global__ void __launch_bounds__(256) k_scan_gw(int ngw) {
    int b = blockIdx.x, tid = threadIdx.x;
    unsigned int* row = g_warpcnt + (size_t)b * ngw;
    int per = (ngw + 255) >> 8;
    int base = tid * per;
    unsigned int s = 0;
    for (int k = 0; k < per; k++) { int i = base + k; if (i < ngw) s += row[i]; }
    __shared__ unsigned int sh[256];
    sh[tid] = s;
    __syncthreads();
    #pragma unroll
    for (int off = 1; off < 256; off <<= 1) {
        unsigned int v = (tid >= off) ? sh[tid - off] : 0;
        __syncthreads();
        if (tid >= off) sh[tid] += v;
        __syncthreads();
    }
    unsigned int incl = sh[tid];
    if (tid == 255) g_bintot[b] = incl;
    unsigned int run = incl - s;
    for (int k = 0; k < per; k++) {
        int i = base + k;
        if (i < ngw) { unsigned int v = row[i]; row[i] = run; run += v; }
    }
}

// ---------------- Pass 2b: scan 64 bin totals ----------------
__global__ void k_scan_bins() {
    int tid = threadIdx.x;
    unsigned int v = g_bintot[tid];
    __shared__ unsigned int sh[64];
    sh[tid] = v;
    __syncthreads();
    for (int off = 1; off < 64; off <<= 1) {
        unsigned int u = (tid >= off) ? sh[tid - off] : 0;
        __syncthreads();
        if (tid >= off) sh[tid] += u;
        __syncthreads();
    }
    g_binbase[tid] = sh[tid] - v;
}

// ---------------- Pass 3: pure gather + interpolate + scatter ----------------
__global__ void __launch_bounds__(CTA1) k_sample(const float* __restrict__ xyz,
                                                 const float* __restrict__ vol,
                                                 const float* __restrict__ dmin,
                                                 const float* __restrict__ dmax,
                                                 float* __restrict__ out,
                                                 int ngw) {
    __shared__ float s_org[NBIN * 3];
    __shared__ float s_scl[NBIN * 3];
    __shared__ unsigned int s_wb[NW * NBIN];
    int tid = threadIdx.x, w = tid >> 5, lane = tid & 31;

    for (int i = tid; i < NBIN * 3; i += CTA1) {
        float dn = dmin[i];
        s_org[i] = dn;
        s_scl[i] = 63.0f / (dmax[i] - dn);     // f = (p-dmin)*63/(dmax-dmin)
    }
    int gw = blockIdx.x * NW + w;
    s_wb[w * NBIN + lane]      = g_binbase[lane]      + g_warpcnt[(size_t)lane * ngw + gw];
    s_wb[w * NBIN + 32 + lane] = g_binbase[lane + 32] + g_warpcnt[(size_t)(lane + 32) * ngw + gw];
    __syncthreads();

    const unsigned int* wb = s_wb + w * NBIN;
    size_t segbase = (size_t)gw * SEG;

    #pragma unroll 4
    for (int r = 0; r < RND; r++) {
        size_t p = segbase + (size_t)r * 32 + lane;
        const float* q = xyz + p * 3;
        float x = __ldg(q + 0), y = __ldg(q + 1), z = __ldg(q + 2);
        unsigned int pk = g_rank[p];
        int bid = pk >> 10;
        unsigned int rank = pk & 1023u;
        int b3 = bid * 3;

        float fx = (x - s_org[b3 + 0]) * s_scl[b3 + 0];
        float fy = (y - s_org[b3 + 1]) * s_scl[b3 + 1];
        float fz = (z - s_org[b3 + 2]) * s_scl[b3 + 2];
        float x0f = floorf(fx), y0f = floorf(fy), z0f = floorf(fz);
        float wx = fx - x0f, wy = fy - y0f, wz = fz - z0f;
        int x0 = (int)x0f, y0 = (int)y0f, z0 = (int)z0f;
        int x0c = min(max(x0, 0), 63), x1c = min(max(x0 + 1, 0), 63);
        int y0c = min(max(y0, 0), 63), y1c = min(max(y0 + 1, 0), 63);
        int z0c = min(max(z0, 0), 63), z1c = min(max(z0 + 1, 0), 63);

        const float* vb = vol + ((size_t)bid << 18);
        int zy00 = ((z0c << 6) + y0c) << 6;
        int zy01 = ((z0c << 6) + y1c) << 6;
        int zy10 = ((z1c << 6) + y0c) << 6;
        int zy11 = ((z1c << 6) + y1c) << 6;

        float v000 = __ldg(vb + zy00 + x0c), v001 = __ldg(vb + zy00 + x1c);
        float v010 = __ldg(vb + zy01 + x0c), v011 = __ldg(vb + zy01 + x1c);
        float v100 = __ldg(vb + zy10 + x0c), v101 = __ldg(vb + zy10 + x1c);
        float v110 = __ldg(vb + zy11 + x0c), v111 = __ldg(vb + zy11 + x1c);

        float omx = 1.0f - wx, omy = 1.0f - wy, omz = 1.0f - wz;
        float res = omz * (omy * (omx * v000 + wx * v001) + wy * (omx * v010 + wx * v011))
                  + wz  * (omy * (omx * v100 + wx * v101) + wy * (omx * v110 + wx * v111));

        out[wb[bid] + rank] = res;
    }
}

extern "C" void kernel_launch(void* const* d_in, const int* in_sizes, int n_in,
                              void* d_out, int out_size) {
    const float* xyz  = (const float*)d_in[0];
    const float* aabb = (const float*)d_in[1];
    const float* vol  = (const float*)d_in[2];
    const float* dmin = (const float*)d_in[3];
    const float* dmax = (const float*)d_in[4];
    float* out = (float*)d_out;

    int n   = in_sizes[0] / 3;      // 4,194,304
    int ngw = n / SEG;              // 8192 warps
    int ncta = ngw / NW;            // 1024 CTAs

    k_bin<<<ncta, CTA1>>>(xyz, aabb, ngw);
    k_scan_gw<<<NBIN, 256>>>(ngw);
    k_scan_bins<<<1, NBIN>>>();
    k_sample<<<ncta, CTA1>>>(xyz, vol, dmin, dmax, out, ngw);
}